// round 2
// baseline (speedup 1.0000x reference)
#include <cuda_runtime.h>

#define B_   2048
#define L_   64
#define N_   1024
#define E_   32
#define SE_  16
#define F_   8
#define NSH  56      // E + F + SE
#define NF   59      // NSH + 3
#define S_   20
#define G    4       // batch rows per block
#define T    256     // threads per block

// transposed conv weights: conv_wT[j][n] = conv_w[n][j]   (59 * 1024 floats = 236 KB)
__device__ __align__(256) float g_convT[NF * N_];

__global__ void transpose_conv_kernel(const float* __restrict__ conv_w) {
    int o = blockIdx.x * blockDim.x + threadIdx.x;
    if (o < NF * N_) {
        int j = o / N_;
        int n = o - j * N_;
        g_convT[o] = conv_w[n * NF + j];
    }
}

__global__ __launch_bounds__(T, 6) void markov_fused_kernel(
    const float* __restrict__ x,          // [B, L, N]
    const float* __restrict__ x_dist,     // [N]
    const float* __restrict__ x_features, // [B, F]
    const float* __restrict__ x_markov,   // [B, N]
    const int*   __restrict__ stops,      // [B, S]
    const int*   __restrict__ x_week,     // [B]
    const int*   __restrict__ x_mask,     // [B, N]
    const float* __restrict__ stop_emb,   // [N, SE]
    const float* __restrict__ week_emb,   // [NW, E]
    const float* __restrict__ conv_b,     // [N]
    const float* __restrict__ fc1_w,      // [L]
    const float* __restrict__ fc1_b,      // scalar
    float*       __restrict__ out)        // [B, N]
{
    __shared__ float s_w[L_];
    __shared__ float s_sh[G][NSH];
    __shared__ float s_red[G][8];

    const int tid  = threadIdx.x;
    const int lane = tid & 31;
    const int warp = tid >> 5;
    const int b0   = blockIdx.x * G;

    if (tid < L_) s_w[tid] = fc1_w[tid];

    // shared (node-independent) features per b-row: [week_emb(32) | features(8) | sum stop_emb(16)]
    {
        int g = tid >> 6;      // 0..3  (T/64 == G)
        int j = tid & 63;
        if (j < NSH) {
            int b = b0 + g;
            float v;
            if (j < E_) {
                v = week_emb[x_week[b] * E_ + j];
            } else if (j < E_ + F_) {
                v = x_features[b * F_ + (j - E_)];
            } else {
                int c = j - E_ - F_;
                float s = 0.f;
                #pragma unroll
                for (int st = 0; st < S_; ++st)
                    s += stop_emb[stops[b * S_ + st] * SE_ + c];
                v = s;
            }
            s_sh[g][j] = v;
        }
    }
    __syncthreads();

    // ---- main HBM-bound pass: out[b,n] = sum_l fc1_w[l] * x[b,l,n] ----
    float4 acc[G];
    #pragma unroll
    for (int g = 0; g < G; ++g) acc[g] = make_float4(0.f, 0.f, 0.f, 0.f);

    const float4* xb = (const float4*)(x + (size_t)b0 * (L_ * N_)) + tid;
    #pragma unroll 2
    for (int l = 0; l < L_; ++l) {
        float wl = s_w[l];
        #pragma unroll
        for (int g = 0; g < G; ++g) {
            float4 xv = __ldcs(xb + (size_t)g * (L_ * N_ / 4) + (size_t)l * (N_ / 4));
            acc[g].x = fmaf(wl, xv.x, acc[g].x);
            acc[g].y = fmaf(wl, xv.y, acc[g].y);
            acc[g].z = fmaf(wl, xv.z, acc[g].z);
            acc[g].w = fmaf(wl, xv.w, acc[g].w);
        }
    }

    // ---- 56-term dot with node kernels (coalesced via transposed weights) ----
    float d[G][4];
    #pragma unroll
    for (int g = 0; g < G; ++g)
        d[g][0] = d[g][1] = d[g][2] = d[g][3] = 0.f;

    #pragma unroll 8
    for (int j = 0; j < NSH; ++j) {
        float4 wv = *(const float4*)(&g_convT[j * N_ + tid * 4]);
        #pragma unroll
        for (int g = 0; g < G; ++g) {
            float sh = s_sh[g][j];
            d[g][0] = fmaf(sh, wv.x, d[g][0]);
            d[g][1] = fmaf(sh, wv.y, d[g][1]);
            d[g][2] = fmaf(sh, wv.z, d[g][2]);
            d[g][3] = fmaf(sh, wv.w, d[g][3]);
        }
    }

    float4 w56 = *(const float4*)(&g_convT[(NSH + 0) * N_ + tid * 4]);
    float4 w57 = *(const float4*)(&g_convT[(NSH + 1) * N_ + tid * 4]);
    float4 w58 = *(const float4*)(&g_convT[(NSH + 2) * N_ + tid * 4]);
    float4 cb  = *(const float4*)(&conv_b[tid * 4]);
    float4 xd  = *(const float4*)(&x_dist[tid * 4]);
    float  fb  = *fc1_b;

    float lg[G][4];
    #pragma unroll
    for (int g = 0; g < G; ++g) {
        float4 xm = *(const float4*)(&x_markov[(size_t)(b0 + g) * N_ + tid * 4]);
        lg[g][0] = d[g][0] + (acc[g].x + fb) * w56.x + xd.x * w57.x + xm.x * w58.x + cb.x;
        lg[g][1] = d[g][1] + (acc[g].y + fb) * w56.y + xd.y * w57.y + xm.y * w58.y + cb.y;
        lg[g][2] = d[g][2] + (acc[g].z + fb) * w56.z + xd.z * w57.z + xm.z * w58.z + cb.z;
        lg[g][3] = d[g][3] + (acc[g].w + fb) * w56.w + xd.w * w57.w + xm.w * w58.w + cb.w;
    }

    // ---- log_softmax over n (per b-row) ----
    float mg[G];
    #pragma unroll
    for (int g = 0; g < G; ++g)
        mg[g] = fmaxf(fmaxf(lg[g][0], lg[g][1]), fmaxf(lg[g][2], lg[g][3]));
    #pragma unroll
    for (int off = 16; off > 0; off >>= 1) {
        #pragma unroll
        for (int g = 0; g < G; ++g)
            mg[g] = fmaxf(mg[g], __shfl_xor_sync(0xffffffffu, mg[g], off));
    }
    if (lane == 0) {
        #pragma unroll
        for (int g = 0; g < G; ++g) s_red[g][warp] = mg[g];
    }
    __syncthreads();
    #pragma unroll
    for (int g = 0; g < G; ++g) {
        float m = s_red[g][0];
        #pragma unroll
        for (int w = 1; w < 8; ++w) m = fmaxf(m, s_red[g][w]);
        mg[g] = m;
    }
    __syncthreads();

    float sg[G];
    #pragma unroll
    for (int g = 0; g < G; ++g) {
        sg[g] = __expf(lg[g][0] - mg[g]) + __expf(lg[g][1] - mg[g])
              + __expf(lg[g][2] - mg[g]) + __expf(lg[g][3] - mg[g]);
    }
    #pragma unroll
    for (int off = 16; off > 0; off >>= 1) {
        #pragma unroll
        for (int g = 0; g < G; ++g)
            sg[g] += __shfl_xor_sync(0xffffffffu, sg[g], off);
    }
    if (lane == 0) {
        #pragma unroll
        for (int g = 0; g < G; ++g) s_red[g][warp] = sg[g];
    }
    __syncthreads();
    float lse[G];
    #pragma unroll
    for (int g = 0; g < G; ++g) {
        float s = 0.f;
        #pragma unroll
        for (int w = 0; w < 8; ++w) s += s_red[g][w];
        lse[g] = mg[g] + logf(s);
    }

    // ---- mask + store ----
    #pragma unroll
    for (int g = 0; g < G; ++g) {
        size_t base = (size_t)(b0 + g) * N_ + (size_t)tid * 4;
        int4 mk = *(const int4*)(&x_mask[base]);
        float4 o;
        o.x = mk.x ? -1e8f : (lg[g][0] - lse[g]);
        o.y = mk.y ? -1e8f : (lg[g][1] - lse[g]);
        o.z = mk.z ? -1e8f : (lg[g][2] - lse[g]);
        o.w = mk.w ? -1e8f : (lg[g][3] - lse[g]);
        *(float4*)(&out[base]) = o;
    }
}

extern "C" void kernel_launch(void* const* d_in, const int* in_sizes, int n_in,
                              void* d_out, int out_size) {
    const float* x          = (const float*)d_in[0];
    const float* x_dist     = (const float*)d_in[1];
    const float* x_features = (const float*)d_in[2];
    const float* x_markov   = (const float*)d_in[3];
    const int*   stops      = (const int*)  d_in[4];
    const int*   x_week     = (const int*)  d_in[5];
    const int*   x_mask     = (const int*)  d_in[6];
    const float* stop_emb   = (const float*)d_in[7];
    const float* week_emb   = (const float*)d_in[8];
    const float* conv_w     = (const float*)d_in[9];
    const float* conv_b     = (const float*)d_in[10];
    const float* fc1_w      = (const float*)d_in[11];
    const float* fc1_b      = (const float*)d_in[12];
    float*       out        = (float*)d_out;

    transpose_conv_kernel<<<(NF * N_ + 255) / 256, 256>>>(conv_w);
    markov_fused_kernel<<<B_ / G, T>>>(
        x, x_dist, x_features, x_markov, stops, x_week, x_mask,
        stop_emb, week_emb, conv_b, fc1_w, fc1_b, out);
}

// round 3
// speedup vs baseline: 1.0661x; 1.0661x over previous
#include <cuda_runtime.h>

#define B_   2048
#define L_   64
#define N_   1024
#define E_   32
#define SE_  16
#define F_   8
#define NSH  56      // E + F + SE
#define NF   59      // NSH + 3
#define S_   20
#define G2   8       // batch rows per block in base_kernel
#define T    256

// transposed conv weights: conv_wT[j][n] = conv_w[n][j]   (59 * 1024 floats = 236 KB)
__device__ __align__(256) float g_convT[NF * N_];
// per-(b,n) node-independent part of the logits (8 MB scratch)
__device__ __align__(256) float g_base[B_ * N_];

__global__ void transpose_conv_kernel(const float* __restrict__ conv_w) {
    int o = blockIdx.x * blockDim.x + threadIdx.x;
    if (o < NF * N_) {
        int j = o / N_;
        int n = o - j * N_;
        g_convT[o] = conv_w[n * NF + j];
    }
}

// base[b,n] = sum_j shared[b,j]*convT[j,n] + x_dist[n]*w57[n] + x_markov[b,n]*w58[n]
//           + conv_b[n] + fc1_b*w56[n]
__global__ __launch_bounds__(T) void base_kernel(
    const float* __restrict__ x_dist,
    const float* __restrict__ x_features,
    const float* __restrict__ x_markov,
    const int*   __restrict__ stops,
    const int*   __restrict__ x_week,
    const float* __restrict__ stop_emb,
    const float* __restrict__ week_emb,
    const float* __restrict__ conv_b,
    const float* __restrict__ fc1_b)
{
    __shared__ float s_sh[G2][NSH];
    const int tid = threadIdx.x;
    const int b0  = blockIdx.x * G2;

    for (int idx = tid; idx < G2 * NSH; idx += T) {
        int g = idx / NSH;
        int j = idx - g * NSH;
        int b = b0 + g;
        float v;
        if (j < E_) {
            v = week_emb[x_week[b] * E_ + j];
        } else if (j < E_ + F_) {
            v = x_features[b * F_ + (j - E_)];
        } else {
            int c = j - E_ - F_;
            float s = 0.f;
            #pragma unroll
            for (int st = 0; st < S_; ++st)
                s += stop_emb[stops[b * S_ + st] * SE_ + c];
            v = s;
        }
        s_sh[g][j] = v;
    }
    __syncthreads();

    float d[G2][4];
    #pragma unroll
    for (int g = 0; g < G2; ++g)
        d[g][0] = d[g][1] = d[g][2] = d[g][3] = 0.f;

    #pragma unroll 4
    for (int j = 0; j < NSH; ++j) {
        float4 wv = *(const float4*)(&g_convT[j * N_ + tid * 4]);
        #pragma unroll
        for (int g = 0; g < G2; ++g) {
            float sh = s_sh[g][j];
            d[g][0] = fmaf(sh, wv.x, d[g][0]);
            d[g][1] = fmaf(sh, wv.y, d[g][1]);
            d[g][2] = fmaf(sh, wv.z, d[g][2]);
            d[g][3] = fmaf(sh, wv.w, d[g][3]);
        }
    }

    float4 w56 = *(const float4*)(&g_convT[(NSH + 0) * N_ + tid * 4]);
    float4 w57 = *(const float4*)(&g_convT[(NSH + 1) * N_ + tid * 4]);
    float4 w58 = *(const float4*)(&g_convT[(NSH + 2) * N_ + tid * 4]);
    float4 cb  = *(const float4*)(&conv_b[tid * 4]);
    float4 xd  = *(const float4*)(&x_dist[tid * 4]);
    float  fb  = *fc1_b;

    // node-only constant part
    float4 cst;
    cst.x = xd.x * w57.x + cb.x + fb * w56.x;
    cst.y = xd.y * w57.y + cb.y + fb * w56.y;
    cst.z = xd.z * w57.z + cb.z + fb * w56.z;
    cst.w = xd.w * w57.w + cb.w + fb * w56.w;

    #pragma unroll
    for (int g = 0; g < G2; ++g) {
        size_t base = (size_t)(b0 + g) * N_ + (size_t)tid * 4;
        float4 xm = *(const float4*)(&x_markov[base]);
        float4 o;
        o.x = d[g][0] + xm.x * w58.x + cst.x;
        o.y = d[g][1] + xm.y * w58.y + cst.y;
        o.z = d[g][2] + xm.z * w58.z + cst.z;
        o.w = d[g][3] + xm.w * w58.w + cst.w;
        *(float4*)(&g_base[base]) = o;
    }
}

// hot streaming kernel: one block per batch row
__global__ __launch_bounds__(T, 8) void main_kernel(
    const float* __restrict__ x,      // [B, L, N]
    const int*   __restrict__ x_mask, // [B, N]
    const float* __restrict__ fc1_w,  // [L]
    float*       __restrict__ out)    // [B, N]
{
    __shared__ float s_w[L_];
    __shared__ float s_red[8];

    const int tid  = threadIdx.x;
    const int lane = tid & 31;
    const int warp = tid >> 5;
    const int b    = blockIdx.x;

    if (tid < L_) s_w[tid] = fc1_w[tid];
    __syncthreads();

    const float4* xb = (const float4*)(x + (size_t)b * (L_ * N_)) + tid;
    float4 acc = make_float4(0.f, 0.f, 0.f, 0.f);
    #pragma unroll 4
    for (int l = 0; l < L_; ++l) {
        float4 xv = xb[(size_t)l * (N_ / 4)];
        float wl = s_w[l];
        acc.x = fmaf(wl, xv.x, acc.x);
        acc.y = fmaf(wl, xv.y, acc.y);
        acc.z = fmaf(wl, xv.z, acc.z);
        acc.w = fmaf(wl, xv.w, acc.w);
    }

    size_t base = (size_t)b * N_ + (size_t)tid * 4;
    float4 bs  = *(const float4*)(&g_base[base]);
    float4 w56 = *(const float4*)(&g_convT[NSH * N_ + tid * 4]);

    float lg0 = bs.x + acc.x * w56.x;
    float lg1 = bs.y + acc.y * w56.y;
    float lg2 = bs.z + acc.z * w56.z;
    float lg3 = bs.w + acc.w * w56.w;

    // ---- log_softmax over the 1024 nodes ----
    float m = fmaxf(fmaxf(lg0, lg1), fmaxf(lg2, lg3));
    #pragma unroll
    for (int off = 16; off > 0; off >>= 1)
        m = fmaxf(m, __shfl_xor_sync(0xffffffffu, m, off));
    if (lane == 0) s_red[warp] = m;
    __syncthreads();
    m = s_red[0];
    #pragma unroll
    for (int w = 1; w < 8; ++w) m = fmaxf(m, s_red[w]);
    __syncthreads();

    float s = __expf(lg0 - m) + __expf(lg1 - m) + __expf(lg2 - m) + __expf(lg3 - m);
    #pragma unroll
    for (int off = 16; off > 0; off >>= 1)
        s += __shfl_xor_sync(0xffffffffu, s, off);
    if (lane == 0) s_red[warp] = s;
    __syncthreads();
    s = 0.f;
    #pragma unroll
    for (int w = 0; w < 8; ++w) s += s_red[w];
    float lse = m + logf(s);

    int4 mk = *(const int4*)(&x_mask[base]);
    float4 o;
    o.x = mk.x ? -1e8f : (lg0 - lse);
    o.y = mk.y ? -1e8f : (lg1 - lse);
    o.z = mk.z ? -1e8f : (lg2 - lse);
    o.w = mk.w ? -1e8f : (lg3 - lse);
    *(float4*)(&out[base]) = o;
}

extern "C" void kernel_launch(void* const* d_in, const int* in_sizes, int n_in,
                              void* d_out, int out_size) {
    const float* x          = (const float*)d_in[0];
    const float* x_dist     = (const float*)d_in[1];
    const float* x_features = (const float*)d_in[2];
    const float* x_markov   = (const float*)d_in[3];
    const int*   stops      = (const int*)  d_in[4];
    const int*   x_week     = (const int*)  d_in[5];
    const int*   x_mask     = (const int*)  d_in[6];
    const float* stop_emb   = (const float*)d_in[7];
    const float* week_emb   = (const float*)d_in[8];
    const float* conv_w     = (const float*)d_in[9];
    const float* conv_b     = (const float*)d_in[10];
    const float* fc1_w      = (const float*)d_in[11];
    const float* fc1_b      = (const float*)d_in[12];
    float*       out        = (float*)d_out;

    transpose_conv_kernel<<<(NF * N_ + 255) / 256, 256>>>(conv_w);
    base_kernel<<<B_ / G2, T>>>(x_dist, x_features, x_markov, stops, x_week,
                                stop_emb, week_emb, conv_b, fc1_b);
    main_kernel<<<B_, T>>>(x, x_mask, fc1_w, out);
}